// round 14
// baseline (speedup 1.0000x reference)
#include <cuda_runtime.h>
#include <cuda_fp16.h>
#include <math_constants.h>
#include <cstdint>

#define N_NODES 50000
#define N_EDGES 1600000
#define IN_C 256
#define HID_C 128
#define OUT_C 16
#define HEADS 8
#define NEG_SLOPE 0.2f

#define N_PAD 53248              // 52 * 1024, for the vectorized scan

// ---------------- scratch (device globals; no allocation allowed) ----------------
__device__ __align__(16) __half g_h1h[N_NODES * HID_C];   // layer-1 features fp16 (gather payload)
__device__ __align__(16) float  g_h2[N_NODES * HID_C];    // layer-1 output (post bias+relu)
__device__ __align__(16) __half g_g2h[N_NODES * OUT_C];   // layer-2 features fp16 (gather payload)
__device__ __align__(16) uint2  g_Bfrag[16 * 16 * 32];    // W1 in mma B-fragment layout (64KB)
// paired layout: [n][p][2] holds (head p, head p+4) — one float2 per agg1 lane
__device__ __align__(8) float g_asrc1[N_NODES * HEADS];
__device__ __align__(8) float g_adst1[N_NODES * HEADS];
__device__ float g_asrc2[N_NODES];
__device__ float g_adst2[N_NODES];
__device__ int   g_deg[N_PAD];
__device__ int   g_rowptr[N_PAD + 8];
__device__ int   g_cursor[N_PAD + 8];
__device__ int   g_adj[N_EDGES];

__device__ __forceinline__ float leaky(float a) { return (a > 0.f) ? a : NEG_SLOPE * a; }

__device__ __forceinline__ uint32_t smem_u32(const void* p) {
    uint32_t a;
    asm("{ .reg .u64 t; cvta.to.shared.u64 t, %1; cvt.u32.u64 %0, t; }" : "=r"(a) : "l"(p));
    return a;
}

// ---------------- W1 -> mma B-fragment layout (runs once per call, tiny) ----------------
__global__ void prep_bfrag_kernel(const float* __restrict__ W1) {
    int idx = blockIdx.x * blockDim.x + threadIdx.x;   // 8192
    int lane = idx & 31;
    int ntile = (idx >> 5) & 15;
    int kstep = idx >> 9;
    int n = ntile * 8 + (lane >> 2);
    int k0 = kstep * 16 + (lane & 3) * 2;
    __half2 b0 = __floats2half2_rn(W1[k0 * HID_C + n],       W1[(k0 + 1) * HID_C + n]);
    __half2 b1 = __floats2half2_rn(W1[(k0 + 8) * HID_C + n], W1[(k0 + 9) * HID_C + n]);
    uint2 v;
    v.x = *(uint32_t*)&b0;
    v.y = *(uint32_t*)&b1;
    g_Bfrag[idx] = v;
}

// ---------------- GEMM1 via mma.sync (HMMA), double-buffered, fused attn dots ----------------
#define ASTRIDE 40   // halves; 80B row stride -> conflict-free ldmatrix
__global__ __launch_bounds__(256, 2) void gemm1_mma_kernel(const float* __restrict__ A,
                                                           const float* __restrict__ att_src,
                                                           const float* __restrict__ att_dst,
                                                           int M) {
    __shared__ __align__(16) __half As[2][128][ASTRIDE];
    int tid = threadIdx.x, wid = tid >> 5, lane = tid & 31;
    int warp_m = wid >> 2, warp_n = wid & 3;
    int bm = blockIdx.x * 128;

    float acc[4][4][4];
#pragma unroll
    for (int mt = 0; mt < 4; mt++)
#pragma unroll
        for (int nt = 0; nt < 4; nt++)
#pragma unroll
            for (int r = 0; r < 4; r++) acc[mt][nt][r] = 0.f;

    uint32_t aBase0 = smem_u32(&As[0][0][0]) +
                      ((uint32_t)((warp_m * 64 + (lane & 15)) * ASTRIDE + (lane >> 4) * 8) << 1);
    const uint32_t bufBytes = 128 * ASTRIDE * 2;

    int lr = tid >> 1;
    int lc = (tid & 1) * 16;
    int grow_l = bm + lr;
    const float4* arow = (const float4*)&A[(size_t)grow_l * IN_C];
    bool inM = (grow_l < M);

    // preload + store chunk 0
    {
        float4 v[4];
#pragma unroll
        for (int i = 0; i < 4; i++)
            v[i] = inM ? arow[lc / 4 + i] : make_float4(0.f, 0.f, 0.f, 0.f);
        __half2 h0 = __floats2half2_rn(v[0].x, v[0].y);
        __half2 h1 = __floats2half2_rn(v[0].z, v[0].w);
        __half2 h2 = __floats2half2_rn(v[1].x, v[1].y);
        __half2 h3 = __floats2half2_rn(v[1].z, v[1].w);
        __half2 h4 = __floats2half2_rn(v[2].x, v[2].y);
        __half2 h5 = __floats2half2_rn(v[2].z, v[2].w);
        __half2 h6 = __floats2half2_rn(v[3].x, v[3].y);
        __half2 h7 = __floats2half2_rn(v[3].z, v[3].w);
        *(uint4*)&As[0][lr][lc]     = make_uint4(*(uint32_t*)&h0, *(uint32_t*)&h1,
                                                 *(uint32_t*)&h2, *(uint32_t*)&h3);
        *(uint4*)&As[0][lr][lc + 8] = make_uint4(*(uint32_t*)&h4, *(uint32_t*)&h5,
                                                 *(uint32_t*)&h6, *(uint32_t*)&h7);
    }
    __syncthreads();

    for (int chunk = 0; chunk < 8; chunk++) {
        int cur = chunk & 1;
        // load next chunk's A into registers (completes under the MMAs)
        float4 vn[4];
#pragma unroll
        for (int i = 0; i < 4; i++)
            vn[i] = (chunk < 7 && inM) ? arow[((chunk + 1) * 32 + lc) / 4 + i]
                                       : make_float4(0.f, 0.f, 0.f, 0.f);

        uint32_t aBase = aBase0 + cur * bufBytes;
#pragma unroll
        for (int s = 0; s < 2; s++) {
            int ks = chunk * 2 + s;
            uint2 bf[4];
            const uint2* bp = &g_Bfrag[(ks * 16 + warp_n * 4) * 32 + lane];
#pragma unroll
            for (int nt = 0; nt < 4; nt++) bf[nt] = bp[nt * 32];
            uint32_t af[4][4];
#pragma unroll
            for (int mt = 0; mt < 4; mt++) {
                uint32_t addr = aBase + ((uint32_t)(mt * 16 * ASTRIDE + s * 16) << 1);
                asm volatile(
                    "ldmatrix.sync.aligned.m8n8.x4.shared.b16 {%0,%1,%2,%3}, [%4];"
                    : "=r"(af[mt][0]), "=r"(af[mt][1]), "=r"(af[mt][2]), "=r"(af[mt][3])
                    : "r"(addr));
            }
#pragma unroll
            for (int mt = 0; mt < 4; mt++)
#pragma unroll
                for (int nt = 0; nt < 4; nt++)
                    asm volatile(
                        "mma.sync.aligned.m16n8k16.row.col.f32.f16.f16.f32 "
                        "{%0,%1,%2,%3}, {%4,%5,%6,%7}, {%8,%9}, {%0,%1,%2,%3};"
                        : "+f"(acc[mt][nt][0]), "+f"(acc[mt][nt][1]),
                          "+f"(acc[mt][nt][2]), "+f"(acc[mt][nt][3])
                        : "r"(af[mt][0]), "r"(af[mt][1]), "r"(af[mt][2]), "r"(af[mt][3]),
                          "r"(bf[nt].x), "r"(bf[nt].y));
        }
        // convert + store next chunk into the other buffer
        if (chunk < 7) {
            __half2 h0 = __floats2half2_rn(vn[0].x, vn[0].y);
            __half2 h1 = __floats2half2_rn(vn[0].z, vn[0].w);
            __half2 h2 = __floats2half2_rn(vn[1].x, vn[1].y);
            __half2 h3 = __floats2half2_rn(vn[1].z, vn[1].w);
            __half2 h4 = __floats2half2_rn(vn[2].x, vn[2].y);
            __half2 h5 = __floats2half2_rn(vn[2].z, vn[2].w);
            __half2 h6 = __floats2half2_rn(vn[3].x, vn[3].y);
            __half2 h7 = __floats2half2_rn(vn[3].z, vn[3].w);
            *(uint4*)&As[cur ^ 1][lr][lc]     = make_uint4(*(uint32_t*)&h0, *(uint32_t*)&h1,
                                                           *(uint32_t*)&h2, *(uint32_t*)&h3);
            *(uint4*)&As[cur ^ 1][lr][lc + 8] = make_uint4(*(uint32_t*)&h4, *(uint32_t*)&h5,
                                                           *(uint32_t*)&h6, *(uint32_t*)&h7);
        }
        __syncthreads();
    }

    // ---- epilogue: fp16 store + per-head attention dots (quad-local) ----
    int r0 = lane >> 2;
    int cq = (lane & 3) * 2;
    // per-lane attention coefficient columns
    float asv[8], adv[8];
#pragma unroll
    for (int nt = 0; nt < 4; nt++) {
        int col = warp_n * 32 + nt * 8 + cq;
        asv[2 * nt]     = att_src[col];
        asv[2 * nt + 1] = att_src[col + 1];
        adv[2 * nt]     = att_dst[col];
        adv[2 * nt + 1] = att_dst[col + 1];
    }
    int hA = 2 * warp_n, hB = 2 * warp_n + 1;
    int offA = (hA & 3) * 2 + (hA >> 2);   // paired layout offset
    int offB = (hB & 3) * 2 + (hB >> 2);

#pragma unroll
    for (int mt = 0; mt < 4; mt++) {
        int grow0 = bm + warp_m * 64 + mt * 16 + r0;
        int grow1 = grow0 + 8;
        // fp16 stores
#pragma unroll
        for (int nt = 0; nt < 4; nt++) {
            int col = warp_n * 32 + nt * 8 + cq;
            if (grow0 < M) {
                __half2 h = __floats2half2_rn(acc[mt][nt][0], acc[mt][nt][1]);
                *(__half2*)&g_h1h[(size_t)grow0 * HID_C + col] = h;
            }
            if (grow1 < M) {
                __half2 h = __floats2half2_rn(acc[mt][nt][2], acc[mt][nt][3]);
                *(__half2*)&g_h1h[(size_t)grow1 * HID_C + col] = h;
            }
        }
        // attention dots: head A = cols of nt 0..1, head B = cols of nt 2..3
        float ssA0 = 0.f, ssB0 = 0.f, ssA8 = 0.f, ssB8 = 0.f;
        float sdA0 = 0.f, sdB0 = 0.f, sdA8 = 0.f, sdB8 = 0.f;
#pragma unroll
        for (int nt = 0; nt < 2; nt++) {
            ssA0 = fmaf(acc[mt][nt][0], asv[2 * nt], fmaf(acc[mt][nt][1], asv[2 * nt + 1], ssA0));
            ssA8 = fmaf(acc[mt][nt][2], asv[2 * nt], fmaf(acc[mt][nt][3], asv[2 * nt + 1], ssA8));
            sdA0 = fmaf(acc[mt][nt][0], adv[2 * nt], fmaf(acc[mt][nt][1], adv[2 * nt + 1], sdA0));
            sdA8 = fmaf(acc[mt][nt][2], adv[2 * nt], fmaf(acc[mt][nt][3], adv[2 * nt + 1], sdA8));
        }
#pragma unroll
        for (int nt = 2; nt < 4; nt++) {
            ssB0 = fmaf(acc[mt][nt][0], asv[2 * nt], fmaf(acc[mt][nt][1], asv[2 * nt + 1], ssB0));
            ssB8 = fmaf(acc[mt][nt][2], asv[2 * nt], fmaf(acc[mt][nt][3], asv[2 * nt + 1], ssB8));
            sdB0 = fmaf(acc[mt][nt][0], adv[2 * nt], fmaf(acc[mt][nt][1], adv[2 * nt + 1], sdB0));
            sdB8 = fmaf(acc[mt][nt][2], adv[2 * nt], fmaf(acc[mt][nt][3], adv[2 * nt + 1], sdB8));
        }
#pragma unroll
        for (int off = 1; off <= 2; off <<= 1) {
            ssA0 += __shfl_xor_sync(0xffffffffu, ssA0, off);
            ssB0 += __shfl_xor_sync(0xffffffffu, ssB0, off);
            ssA8 += __shfl_xor_sync(0xffffffffu, ssA8, off);
            ssB8 += __shfl_xor_sync(0xffffffffu, ssB8, off);
            sdA0 += __shfl_xor_sync(0xffffffffu, sdA0, off);
            sdB0 += __shfl_xor_sync(0xffffffffu, sdB0, off);
            sdA8 += __shfl_xor_sync(0xffffffffu, sdA8, off);
            sdB8 += __shfl_xor_sync(0xffffffffu, sdB8, off);
        }
        if ((lane & 3) == 0) {
            if (grow0 < M) {
                g_asrc1[grow0 * HEADS + offA] = ssA0;
                g_asrc1[grow0 * HEADS + offB] = ssB0;
                g_adst1[grow0 * HEADS + offA] = sdA0;
                g_adst1[grow0 * HEADS + offB] = sdB0;
            }
            if (grow1 < M) {
                g_asrc1[grow1 * HEADS + offA] = ssA8;
                g_asrc1[grow1 * HEADS + offB] = ssB8;
                g_adst1[grow1 * HEADS + offA] = sdA8;
                g_adst1[grow1 * HEADS + offB] = sdB8;
            }
        }
    }
}

// ---------------- CSR build (4 edges / thread) ----------------
__global__ void count_kernel(const int* __restrict__ dst, int E) {
    int base = (blockIdx.x * blockDim.x + threadIdx.x) * 4;
    if (base + 3 < E) {
        int4 d = *(const int4*)&dst[base];
        atomicAdd(&g_deg[d.x], 1);
        atomicAdd(&g_deg[d.y], 1);
        atomicAdd(&g_deg[d.z], 1);
        atomicAdd(&g_deg[d.w], 1);
    } else {
        for (int e = base; e < E; e++) atomicAdd(&g_deg[dst[e]], 1);
    }
}

#define SCAN_CH 52    // 52 * 1024 = N_PAD
__global__ __launch_bounds__(1024) void scan_kernel(int N) {
    __shared__ int sums[1024];
    int t = threadIdx.x;
    int base = t * SCAN_CH;
    int4 buf[SCAN_CH / 4];
    const int4 zero4 = make_int4(0, 0, 0, 0);
#pragma unroll
    for (int i = 0; i < SCAN_CH / 4; i++) {
        buf[i] = *(const int4*)&g_deg[base + i * 4];
        *(int4*)&g_deg[base + i * 4] = zero4;   // re-zero for the next replay
    }
    int s = 0;
#pragma unroll
    for (int i = 0; i < SCAN_CH / 4; i++) s += buf[i].x + buf[i].y + buf[i].z + buf[i].w;
    sums[t] = s;
    __syncthreads();
    for (int off = 1; off < 1024; off <<= 1) {
        int v = (t >= off) ? sums[t - off] : 0;
        __syncthreads();
        if (t >= off) sums[t] += v;
        __syncthreads();
    }
    int run = (t == 0) ? 0 : sums[t - 1];
#pragma unroll
    for (int i = 0; i < SCAN_CH / 4; i++) {
        int4 d = buf[i];
        int4 rp;
        rp.x = run; run += d.x;
        rp.y = run; run += d.y;
        rp.z = run; run += d.z;
        rp.w = run; run += d.w;
        *(int4*)&g_rowptr[base + i * 4] = rp;
        *(int4*)&g_cursor[base + i * 4] = rp;
    }
    if (t == 1023) g_rowptr[N_PAD] = sums[1023];
}

__global__ void scatter_kernel(const int* __restrict__ src, const int* __restrict__ dst, int E) {
    int base = (blockIdx.x * blockDim.x + threadIdx.x) * 4;
    if (base + 3 < E) {
        int4 d = *(const int4*)&dst[base];
        int4 sv = *(const int4*)&src[base];
        int p0 = atomicAdd(&g_cursor[d.x], 1);
        int p1 = atomicAdd(&g_cursor[d.y], 1);
        int p2 = atomicAdd(&g_cursor[d.z], 1);
        int p3 = atomicAdd(&g_cursor[d.w], 1);
        g_adj[p0] = sv.x;
        g_adj[p1] = sv.y;
        g_adj[p2] = sv.z;
        g_adj[p3] = sv.w;
    } else {
        for (int e = base; e < E; e++) {
            int pos = atomicAdd(&g_cursor[dst[e]], 1);
            g_adj[pos] = src[e];
        }
    }
}

// ---------------- layer-1 aggregation: 4 edge streams / warp, paired scores ----------------
__global__ __launch_bounds__(256) void agg1_kernel(const float* __restrict__ bias1, int N) {
    int gw = (blockIdx.x * blockDim.x + threadIdx.x) >> 5;
    if (gw >= N) return;
    int lane = threadIdx.x & 31;
    int stream = lane >> 3;     // 4 streams
    int o = lane & 7;
    int head_a = o >> 1;        // pair index p = head_a
    int c_a = o * 8;
    int c_b = 64 + o * 8;

    float2 ad = *(const float2*)&g_adst1[gw * HEADS + head_a * 2];
    float adst_a = ad.x, adst_b = ad.y;

    float s_a = 0.f, s_b = 0.f;
    float acc_a[8], acc_b[8];
#pragma unroll
    for (int j = 0; j < 8; j++) { acc_a[j] = 0.f; acc_b[j] = 0.f; }

    if (stream == 0) {  // self loop
        float2 asl = *(const float2*)&g_asrc1[gw * HEADS + head_a * 2];
        float pa = __expf(leaky(asl.x + adst_a));
        float pb = __expf(leaky(asl.y + adst_b));
        uint4 ra = *(const uint4*)&g_h1h[(size_t)gw * HID_C + c_a];
        uint4 rb = *(const uint4*)&g_h1h[(size_t)gw * HID_C + c_b];
        s_a = pa; s_b = pb;
        uint32_t wa[4] = {ra.x, ra.y, ra.z, ra.w};
        uint32_t wb[4] = {rb.x, rb.y, rb.z, rb.w};
#pragma unroll
        for (int j = 0; j < 4; j++) {
            float2 fa = __half22float2(*(__half2*)&wa[j]);
            float2 fb = __half22float2(*(__half2*)&wb[j]);
            acc_a[2 * j]     = pa * fa.x;
            acc_a[2 * j + 1] = pa * fa.y;
            acc_b[2 * j]     = pb * fb.x;
            acc_b[2 * j + 1] = pb * fb.y;
        }
    }

    int beg = g_rowptr[gw];
    int end = g_rowptr[gw + 1];
#pragma unroll 2
    for (int e = beg + stream; e < end; e += 4) {
        int src = g_adj[e];
        float2 as = *(const float2*)&g_asrc1[src * HEADS + head_a * 2];
        uint4 ra = *(const uint4*)&g_h1h[(size_t)src * HID_C + c_a];
        uint4 rb = *(const uint4*)&g_h1h[(size_t)src * HID_C + c_b];
        float pa = __expf(leaky(as.x + adst_a));
        float pb = __expf(leaky(as.y + adst_b));
        s_a += pa; s_b += pb;
        uint32_t wa[4] = {ra.x, ra.y, ra.z, ra.w};
        uint32_t wb[4] = {rb.x, rb.y, rb.z, rb.w};
#pragma unroll
        for (int j = 0; j < 4; j++) {
            float2 fa = __half22float2(*(__half2*)&wa[j]);
            float2 fb = __half22float2(*(__half2*)&wb[j]);
            acc_a[2 * j]     = fmaf(pa, fa.x, acc_a[2 * j]);
            acc_a[2 * j + 1] = fmaf(pa, fa.y, acc_a[2 * j + 1]);
            acc_b[2 * j]     = fmaf(pb, fb.x, acc_b[2 * j]);
            acc_b[2 * j + 1] = fmaf(pb, fb.y, acc_b[2 * j + 1]);
        }
    }
    // merge the 4 streams
#pragma unroll
    for (int off = 8; off <= 16; off <<= 1) {
        s_a += __shfl_xor_sync(0xffffffffu, s_a, off);
        s_b += __shfl_xor_sync(0xffffffffu, s_b, off);
#pragma unroll
        for (int j = 0; j < 8; j++) {
            acc_a[j] += __shfl_xor_sync(0xffffffffu, acc_a[j], off);
            acc_b[j] += __shfl_xor_sync(0xffffffffu, acc_b[j], off);
        }
    }

    if (stream == 0) {
        float inv_a = 1.f / s_a;
        float inv_b = 1.f / s_b;
        float4 oa0, oa1, ob0, ob1;
        oa0.x = fmaxf(fmaf(acc_a[0], inv_a, bias1[c_a + 0]), 0.f);
        oa0.y = fmaxf(fmaf(acc_a[1], inv_a, bias1[c_a + 1]), 0.f);
        oa0.z = fmaxf(fmaf(acc_a[2], inv_a, bias1[c_a + 2]), 0.f);
        oa0.w = fmaxf(fmaf(acc_a[3], inv_a, bias1[c_a + 3]), 0.f);
        oa1.x = fmaxf(fmaf(acc_a[4], inv_a, bias1[c_a + 4]), 0.f);
        oa1.y = fmaxf(fmaf(acc_a[5], inv_a, bias1[c_a + 5]), 0.f);
        oa1.z = fmaxf(fmaf(acc_a[6], inv_a, bias1[c_a + 6]), 0.f);
        oa1.w = fmaxf(fmaf(acc_a[7], inv_a, bias1[c_a + 7]), 0.f);
        ob0.x = fmaxf(fmaf(acc_b[0], inv_b, bias1[c_b + 0]), 0.f);
        ob0.y = fmaxf(fmaf(acc_b[1], inv_b, bias1[c_b + 1]), 0.f);
        ob0.z = fmaxf(fmaf(acc_b[2], inv_b, bias1[c_b + 2]), 0.f);
        ob0.w = fmaxf(fmaf(acc_b[3], inv_b, bias1[c_b + 3]), 0.f);
        ob1.x = fmaxf(fmaf(acc_b[4], inv_b, bias1[c_b + 4]), 0.f);
        ob1.y = fmaxf(fmaf(acc_b[5], inv_b, bias1[c_b + 5]), 0.f);
        ob1.z = fmaxf(fmaf(acc_b[6], inv_b, bias1[c_b + 6]), 0.f);
        ob1.w = fmaxf(fmaf(acc_b[7], inv_b, bias1[c_b + 7]), 0.f);
        float4* da = (float4*)&g_h2[(size_t)gw * HID_C + c_a];
        float4* db = (float4*)&g_h2[(size_t)gw * HID_C + c_b];
        da[0] = oa0; da[1] = oa1;
        db[0] = ob0; db[1] = ob1;
    }
}

// ---------------- layer 2: g2 = h2 @ W2 (+ attention scores), fused, fp16 out ----------------
__global__ __launch_bounds__(256) void gemm2_kernel(const float* __restrict__ W2,
                                                    const float* __restrict__ att_src,
                                                    const float* __restrict__ att_dst, int N) {
    __shared__ float Ws[HID_C * OUT_C];
    __shared__ float Hs[16][HID_C];
    int tid = threadIdx.x;
    int nodeBase = blockIdx.x * 16;
    for (int i = tid; i < HID_C * OUT_C; i += 256) Ws[i] = W2[i];
    int lnode = tid >> 4;
    int seg = tid & 15;
    int gnode = nodeBase + lnode;
    if (gnode < N) {
        *(float4*)&Hs[lnode][seg * 8]     = *(const float4*)&g_h2[(size_t)gnode * HID_C + seg * 8];
        *(float4*)&Hs[lnode][seg * 8 + 4] = *(const float4*)&g_h2[(size_t)gnode * HID_C + seg * 8 + 4];
    }
    __syncthreads();
    int j = tid & 15;
    float acc = 0.f;
#pragma unroll 8
    for (int c = 0; c < HID_C; c++) acc = fmaf(Hs[lnode][c], Ws[c * OUT_C + j], acc);
    float vs = acc * att_src[j];
    float vd = acc * att_dst[j];
#pragma unroll
    for (int off = 8; off; off >>= 1) {
        vs += __shfl_down_sync(0xffffffffu, vs, off, 16);
        vd += __shfl_down_sync(0xffffffffu, vd, off, 16);
    }
    if (gnode < N) {
        g_g2h[gnode * OUT_C + j] = __float2half_rn(acc);
        if (j == 0) {
            g_asrc2[gnode] = vs;
            g_adst2[gnode] = vd;
        }
    }
}

// ---------------- layer-2 aggregation: 16 edge streams / warp, uint4 fp16 gather ----------------
__global__ __launch_bounds__(256) void agg2_kernel(const float* __restrict__ bias2,
                                                   float* __restrict__ out, int N) {
    int gw = (blockIdx.x * blockDim.x + threadIdx.x) >> 5;
    if (gw >= N) return;
    int lane = threadIdx.x & 31;
    int stream = lane >> 1;     // 16 streams
    int q = lane & 1;           // channels q*8 .. q*8+7

    float adst = g_adst2[gw];
    int beg = g_rowptr[gw];
    int end = g_rowptr[gw + 1];

    float s = 0.f;
    float a[8] = {0.f, 0.f, 0.f, 0.f, 0.f, 0.f, 0.f, 0.f};
    if (stream == 0) {  // self loop
        float p0 = __expf(leaky(g_asrc2[gw] + adst));
        uint4 g = *(const uint4*)&g_g2h[gw * OUT_C + q * 8];
        uint32_t w[4] = {g.x, g.y, g.z, g.w};
        s = p0;
#pragma unroll
        for (int j = 0; j < 4; j++) {
            float2 f = __half22float2(*(__half2*)&w[j]);
            a[2 * j]     = p0 * f.x;
            a[2 * j + 1] = p0 * f.y;
        }
    }
#pragma unroll 2
    for (int e = beg + stream; e < end; e += 16) {
        int src = g_adj[e];
        float p = __expf(leaky(g_asrc2[src] + adst));
        uint4 g = *(const uint4*)&g_g2h[src * OUT_C + q * 8];
        uint32_t w[4] = {g.x, g.y, g.z, g.w};
        s += p;
#pragma unroll
        for (int j = 0; j < 4; j++) {
            float2 f = __half22float2(*(__half2*)&w[j]);
            a[2 * j]     = fmaf(p, f.x, a[2 * j]);
            a[2 * j + 1] = fmaf(p, f.y, a[2 * j + 1]);
        }
    }
#pragma unroll
    for (int off = 2; off <= 16; off <<= 1) {
        s += __shfl_xor_sync(0xffffffffu, s, off);
#pragma unroll
        for (int j = 0; j < 8; j++) a[j] += __shfl_xor_sync(0xffffffffu, a[j], off);
    }
    if (stream == 0) {
        float inv = 1.f / s;
        float4 o0, o1;
        o0.x = fmaf(a[0], inv, bias2[q * 8 + 0]);
        o0.y = fmaf(a[1], inv, bias2[q * 8 + 1]);
        o0.z = fmaf(a[2], inv, bias2[q * 8 + 2]);
        o0.w = fmaf(a[3], inv, bias2[q * 8 + 3]);
        o1.x = fmaf(a[4], inv, bias2[q * 8 + 4]);
        o1.y = fmaf(a[5], inv, bias2[q * 8 + 5]);
        o1.z = fmaf(a[6], inv, bias2[q * 8 + 6]);
        o1.w = fmaf(a[7], inv, bias2[q * 8 + 7]);
        float4* dst = (float4*)&out[gw * OUT_C + q * 8];
        dst[0] = o0;
        dst[1] = o1;
    }
}

// ---------------- launch: fork-join graph ----------------
extern "C" void kernel_launch(void* const* d_in, const int* in_sizes, int n_in,
                              void* d_out, int out_size) {
    const float* x        = (const float*)d_in[0];
    const int*   eidx     = (const int*)d_in[1];
    const float* W1       = (const float*)d_in[2];
    const float* att_src1 = (const float*)d_in[3];
    const float* att_dst1 = (const float*)d_in[4];
    const float* bias1    = (const float*)d_in[5];
    const float* W2       = (const float*)d_in[6];
    const float* att_src2 = (const float*)d_in[7];
    const float* att_dst2 = (const float*)d_in[8];
    const float* bias2    = (const float*)d_in[9];
    float* out = (float*)d_out;

    int N = in_sizes[0] / IN_C;
    int E = in_sizes[1] / 2;
    const int* srcArr = eidx;
    const int* dstArr = eidx + E;

    static cudaStream_t s2 = nullptr;
    static cudaEvent_t evFork = nullptr, evJoin = nullptr;
    if (!s2) {
        cudaStreamCreateWithFlags(&s2, cudaStreamNonBlocking);
        cudaEventCreateWithFlags(&evFork, cudaEventDisableTiming);
        cudaEventCreateWithFlags(&evJoin, cudaEventDisableTiming);
    }

    // fork: CSR build on side stream (g_deg zeroed by the previous call's scan_kernel;
    // static __device__ arrays start zeroed, so the first call is also correct)
    cudaEventRecord(evFork, 0);
    cudaStreamWaitEvent(s2, evFork, 0);
    count_kernel<<<(E / 4 + 255) / 256, 256, 0, s2>>>(dstArr, E);
    scan_kernel<<<1, 1024, 0, s2>>>(N);
    scatter_kernel<<<(E / 4 + 255) / 256, 256, 0, s2>>>(srcArr, dstArr, E);
    cudaEventRecord(evJoin, s2);

    // main stream: B fragments, tensor-core GEMM1 (attn dots fused in epilogue)
    prep_bfrag_kernel<<<32, 256>>>(W1);
    gemm1_mma_kernel<<<(N + 127) / 128, 256>>>(x, att_src1, att_dst1, N);

    // join
    cudaStreamWaitEvent(0, evJoin, 0);

    agg1_kernel<<<(N * 32 + 255) / 256, 256>>>(bias1, N);
    gemm2_kernel<<<(N + 15) / 16, 256>>>(W2, att_src2, att_dst2, N);
    agg2_kernel<<<(N * 32 + 255) / 256, 256>>>(bias2, out, N);
}

// round 15
// speedup vs baseline: 1.0289x; 1.0289x over previous
#include <cuda_runtime.h>
#include <cuda_fp16.h>
#include <math_constants.h>
#include <cstdint>

#define N_NODES 50000
#define N_EDGES 1600000
#define IN_C 256
#define HID_C 128
#define OUT_C 16
#define HEADS 8
#define NEG_SLOPE 0.2f

#define N_PAD 53248              // 52 * 1024, for the vectorized scan

// ---------------- scratch (device globals; no allocation allowed) ----------------
__device__ __align__(16) __half g_h1h[N_NODES * HID_C];   // layer-1 features fp16 (gather payload)
__device__ __align__(16) float  g_h2[N_NODES * HID_C];    // layer-1 output (post bias+relu)
__device__ __align__(16) __half g_g2h[N_NODES * OUT_C];   // layer-2 features fp16 (gather payload)
__device__ __align__(16) uint2  g_Bfrag[16 * 16 * 32];    // W1 in mma B-fragment layout (64KB)
__device__ float g_asrc1[N_NODES * HEADS];
__device__ float g_adst1[N_NODES * HEADS];
__device__ float g_asrc2[N_NODES];
__device__ float g_adst2[N_NODES];
__device__ int   g_deg[N_PAD];
__device__ int   g_rowptr[N_PAD + 8];
__device__ int   g_cursor[N_PAD + 8];
__device__ int   g_adj[N_EDGES];

__device__ __forceinline__ float leaky(float a) { return (a > 0.f) ? a : NEG_SLOPE * a; }

__device__ __forceinline__ uint32_t smem_u32(const void* p) {
    uint32_t a;
    asm("{ .reg .u64 t; cvta.to.shared.u64 t, %1; cvt.u32.u64 %0, t; }" : "=r"(a) : "l"(p));
    return a;
}

// ---------------- W1 -> mma B-fragment layout (runs once per call, tiny) ----------------
__global__ void prep_bfrag_kernel(const float* __restrict__ W1) {
    int idx = blockIdx.x * blockDim.x + threadIdx.x;   // 8192
    int lane = idx & 31;
    int ntile = (idx >> 5) & 15;
    int kstep = idx >> 9;
    int n = ntile * 8 + (lane >> 2);
    int k0 = kstep * 16 + (lane & 3) * 2;
    __half2 b0 = __floats2half2_rn(W1[k0 * HID_C + n],       W1[(k0 + 1) * HID_C + n]);
    __half2 b1 = __floats2half2_rn(W1[(k0 + 8) * HID_C + n], W1[(k0 + 9) * HID_C + n]);
    uint2 v;
    v.x = *(uint32_t*)&b0;
    v.y = *(uint32_t*)&b1;
    g_Bfrag[idx] = v;
}

// ---------------- GEMM1 via mma.sync (HMMA), register double-buffered ----------------
#define ASTRIDE 40   // halves; 80B row stride -> conflict-free ldmatrix
__global__ __launch_bounds__(256, 2) void gemm1_mma_kernel(const float* __restrict__ A, int M) {
    __shared__ __align__(16) __half As[128][ASTRIDE];
    int tid = threadIdx.x, wid = tid >> 5, lane = tid & 31;
    int warp_m = wid >> 2, warp_n = wid & 3;
    int bm = blockIdx.x * 128;

    float acc[4][4][4];
#pragma unroll
    for (int mt = 0; mt < 4; mt++)
#pragma unroll
        for (int nt = 0; nt < 4; nt++)
#pragma unroll
            for (int r = 0; r < 4; r++) acc[mt][nt][r] = 0.f;

    uint32_t aBase = smem_u32(&As[0][0]) +
                     ((uint32_t)((warp_m * 64 + (lane & 15)) * ASTRIDE + (lane >> 4) * 8) << 1);

    int lr = tid >> 1;
    int lc = (tid & 1) * 16;
    int grow_l = bm + lr;
    const float4* arow = (const float4*)&A[(size_t)grow_l * IN_C];
    bool inM = (grow_l < M);

    float4 v[4];
#pragma unroll
    for (int i = 0; i < 4; i++)
        v[i] = inM ? arow[lc / 4 + i] : make_float4(0.f, 0.f, 0.f, 0.f);

    for (int chunk = 0; chunk < 8; chunk++) {
        {
            uint4 s0, s1;
            __half2 h0 = __floats2half2_rn(v[0].x, v[0].y);
            __half2 h1 = __floats2half2_rn(v[0].z, v[0].w);
            __half2 h2 = __floats2half2_rn(v[1].x, v[1].y);
            __half2 h3 = __floats2half2_rn(v[1].z, v[1].w);
            s0 = make_uint4(*(uint32_t*)&h0, *(uint32_t*)&h1, *(uint32_t*)&h2, *(uint32_t*)&h3);
            __half2 h4 = __floats2half2_rn(v[2].x, v[2].y);
            __half2 h5 = __floats2half2_rn(v[2].z, v[2].w);
            __half2 h6 = __floats2half2_rn(v[3].x, v[3].y);
            __half2 h7 = __floats2half2_rn(v[3].z, v[3].w);
            s1 = make_uint4(*(uint32_t*)&h4, *(uint32_t*)&h5, *(uint32_t*)&h6, *(uint32_t*)&h7);
            *(uint4*)&As[lr][lc]     = s0;
            *(uint4*)&As[lr][lc + 8] = s1;
        }
        __syncthreads();

        float4 vn[4];
#pragma unroll
        for (int i = 0; i < 4; i++)
            vn[i] = (chunk < 7 && inM) ? arow[((chunk + 1) * 32 + lc) / 4 + i]
                                       : make_float4(0.f, 0.f, 0.f, 0.f);

#pragma unroll
        for (int s = 0; s < 2; s++) {
            int ks = chunk * 2 + s;
            uint2 bf[4];
            const uint2* bp = &g_Bfrag[(ks * 16 + warp_n * 4) * 32 + lane];
#pragma unroll
            for (int nt = 0; nt < 4; nt++) bf[nt] = bp[nt * 32];
            uint32_t af[4][4];
#pragma unroll
            for (int mt = 0; mt < 4; mt++) {
                uint32_t addr = aBase + ((uint32_t)(mt * 16 * ASTRIDE + s * 16) << 1);
                asm volatile(
                    "ldmatrix.sync.aligned.m8n8.x4.shared.b16 {%0,%1,%2,%3}, [%4];"
                    : "=r"(af[mt][0]), "=r"(af[mt][1]), "=r"(af[mt][2]), "=r"(af[mt][3])
                    : "r"(addr));
            }
#pragma unroll
            for (int mt = 0; mt < 4; mt++)
#pragma unroll
                for (int nt = 0; nt < 4; nt++)
                    asm volatile(
                        "mma.sync.aligned.m16n8k16.row.col.f32.f16.f16.f32 "
                        "{%0,%1,%2,%3}, {%4,%5,%6,%7}, {%8,%9}, {%0,%1,%2,%3};"
                        : "+f"(acc[mt][nt][0]), "+f"(acc[mt][nt][1]),
                          "+f"(acc[mt][nt][2]), "+f"(acc[mt][nt][3])
                        : "r"(af[mt][0]), "r"(af[mt][1]), "r"(af[mt][2]), "r"(af[mt][3]),
                          "r"(bf[nt].x), "r"(bf[nt].y));
        }
        __syncthreads();
#pragma unroll
        for (int i = 0; i < 4; i++) v[i] = vn[i];
    }

    int r0 = lane >> 2;
    int cq = (lane & 3) * 2;
#pragma unroll
    for (int mt = 0; mt < 4; mt++) {
        int grow0 = bm + warp_m * 64 + mt * 16 + r0;
        int grow1 = grow0 + 8;
#pragma unroll
        for (int nt = 0; nt < 4; nt++) {
            int col = warp_n * 32 + nt * 8 + cq;
            if (grow0 < M) {
                __half2 h = __floats2half2_rn(acc[mt][nt][0], acc[mt][nt][1]);
                *(__half2*)&g_h1h[(size_t)grow0 * HID_C + col] = h;
            }
            if (grow1 < M) {
                __half2 h = __floats2half2_rn(acc[mt][nt][2], acc[mt][nt][3]);
                *(__half2*)&g_h1h[(size_t)grow1 * HID_C + col] = h;
            }
        }
    }
}

// ---------------- attention coefficients from fp16 h1 ----------------
__global__ void attn1h_kernel(const float* __restrict__ att_src,
                              const float* __restrict__ att_dst, int N) {
    int idx = blockIdx.x * blockDim.x + threadIdx.x;  // n*8 + h
    if (idx >= N * HEADS) return;
    int h = idx & 7;
    int n = idx >> 3;
    const uint4* hp = (const uint4*)&g_h1h[(size_t)n * HID_C + h * 16];
    uint4 r0 = hp[0], r1 = hp[1];
    uint32_t raw[8] = {r0.x, r0.y, r0.z, r0.w, r1.x, r1.y, r1.z, r1.w};
    float ss = 0.f, sd = 0.f;
#pragma unroll
    for (int j = 0; j < 8; j++) {
        float2 f = __half22float2(*(__half2*)&raw[j]);
        ss = fmaf(f.x, att_src[h * 16 + 2 * j], ss);
        ss = fmaf(f.y, att_src[h * 16 + 2 * j + 1], ss);
        sd = fmaf(f.x, att_dst[h * 16 + 2 * j], sd);
        sd = fmaf(f.y, att_dst[h * 16 + 2 * j + 1], sd);
    }
    g_asrc1[idx] = ss;
    g_adst1[idx] = sd;
}

// ---------------- CSR build (4 edges / thread) ----------------
__global__ void count_kernel(const int* __restrict__ dst, int E) {
    int base = (blockIdx.x * blockDim.x + threadIdx.x) * 4;
    if (base + 3 < E) {
        int4 d = *(const int4*)&dst[base];
        atomicAdd(&g_deg[d.x], 1);
        atomicAdd(&g_deg[d.y], 1);
        atomicAdd(&g_deg[d.z], 1);
        atomicAdd(&g_deg[d.w], 1);
    } else {
        for (int e = base; e < E; e++) atomicAdd(&g_deg[dst[e]], 1);
    }
}

#define SCAN_CH 52    // 52 * 1024 = N_PAD
__global__ __launch_bounds__(1024) void scan_kernel(int N) {
    __shared__ int sums[1024];
    int t = threadIdx.x;
    int base = t * SCAN_CH;
    int4 buf[SCAN_CH / 4];
    const int4 zero4 = make_int4(0, 0, 0, 0);
#pragma unroll
    for (int i = 0; i < SCAN_CH / 4; i++) {
        buf[i] = *(const int4*)&g_deg[base + i * 4];
        *(int4*)&g_deg[base + i * 4] = zero4;   // self-restore for the next graph replay
    }
    int s = 0;
#pragma unroll
    for (int i = 0; i < SCAN_CH / 4; i++) s += buf[i].x + buf[i].y + buf[i].z + buf[i].w;
    sums[t] = s;
    __syncthreads();
    for (int off = 1; off < 1024; off <<= 1) {
        int v = (t >= off) ? sums[t - off] : 0;
        __syncthreads();
        if (t >= off) sums[t] += v;
        __syncthreads();
    }
    int run = (t == 0) ? 0 : sums[t - 1];
#pragma unroll
    for (int i = 0; i < SCAN_CH / 4; i++) {
        int4 d = buf[i];
        int4 rp;
        rp.x = run; run += d.x;
        rp.y = run; run += d.y;
        rp.z = run; run += d.z;
        rp.w = run; run += d.w;
        *(int4*)&g_rowptr[base + i * 4] = rp;
        *(int4*)&g_cursor[base + i * 4] = rp;
    }
    if (t == 1023) g_rowptr[N_PAD] = sums[1023];
}

__global__ void scatter_kernel(const int* __restrict__ src, const int* __restrict__ dst, int E) {
    int base = (blockIdx.x * blockDim.x + threadIdx.x) * 4;
    if (base + 3 < E) {
        int4 d = *(const int4*)&dst[base];
        int4 sv = *(const int4*)&src[base];
        int p0 = atomicAdd(&g_cursor[d.x], 1);
        int p1 = atomicAdd(&g_cursor[d.y], 1);
        int p2 = atomicAdd(&g_cursor[d.z], 1);
        int p3 = atomicAdd(&g_cursor[d.w], 1);
        g_adj[p0] = sv.x;
        g_adj[p1] = sv.y;
        g_adj[p2] = sv.z;
        g_adj[p3] = sv.w;
    } else {
        for (int e = base; e < E; e++) {
            int pos = atomicAdd(&g_cursor[dst[e]], 1);
            g_adj[pos] = src[e];
        }
    }
}

// ---------------- layer-1 aggregation: 4 edge streams / warp (node range) ----------------
__global__ __launch_bounds__(256) void agg1_kernel(const float* __restrict__ bias1,
                                                   int nodeBase, int nodeLimit) {
    int gw = nodeBase + ((blockIdx.x * blockDim.x + threadIdx.x) >> 5);
    if (gw >= nodeLimit) return;
    int lane = threadIdx.x & 31;
    int stream = lane >> 3;     // 4 streams
    int o = lane & 7;
    int head_a = o >> 1;
    int head_b = head_a + 4;
    int c_a = o * 8;
    int c_b = 64 + o * 8;

    float adst_a = g_adst1[gw * HEADS + head_a];
    float adst_b = g_adst1[gw * HEADS + head_b];

    float s_a = 0.f, s_b = 0.f;
    float acc_a[8], acc_b[8];
#pragma unroll
    for (int j = 0; j < 8; j++) { acc_a[j] = 0.f; acc_b[j] = 0.f; }

    if (stream == 0) {  // self loop
        float pa = __expf(leaky(g_asrc1[gw * HEADS + head_a] + adst_a));
        float pb = __expf(leaky(g_asrc1[gw * HEADS + head_b] + adst_b));
        uint4 ra = *(const uint4*)&g_h1h[(size_t)gw * HID_C + c_a];
        uint4 rb = *(const uint4*)&g_h1h[(size_t)gw * HID_C + c_b];
        s_a = pa; s_b = pb;
        uint32_t wa[4] = {ra.x, ra.y, ra.z, ra.w};
        uint32_t wb[4] = {rb.x, rb.y, rb.z, rb.w};
#pragma unroll
        for (int j = 0; j < 4; j++) {
            float2 fa = __half22float2(*(__half2*)&wa[j]);
            float2 fb = __half22float2(*(__half2*)&wb[j]);
            acc_a[2 * j]     = pa * fa.x;
            acc_a[2 * j + 1] = pa * fa.y;
            acc_b[2 * j]     = pb * fb.x;
            acc_b[2 * j + 1] = pb * fb.y;
        }
    }

    int beg = g_rowptr[gw];
    int end = g_rowptr[gw + 1];
#pragma unroll 2
    for (int e = beg + stream; e < end; e += 4) {
        int src = g_adj[e];
        float asa = g_asrc1[src * HEADS + head_a];
        float asb = g_asrc1[src * HEADS + head_b];
        uint4 ra = *(const uint4*)&g_h1h[(size_t)src * HID_C + c_a];
        uint4 rb = *(const uint4*)&g_h1h[(size_t)src * HID_C + c_b];
        float pa = __expf(leaky(asa + adst_a));
        float pb = __expf(leaky(asb + adst_b));
        s_a += pa; s_b += pb;
        uint32_t wa[4] = {ra.x, ra.y, ra.z, ra.w};
        uint32_t wb[4] = {rb.x, rb.y, rb.z, rb.w};
#pragma unroll
        for (int j = 0; j < 4; j++) {
            float2 fa = __half22float2(*(__half2*)&wa[j]);
            float2 fb = __half22float2(*(__half2*)&wb[j]);
            acc_a[2 * j]     = fmaf(pa, fa.x, acc_a[2 * j]);
            acc_a[2 * j + 1] = fmaf(pa, fa.y, acc_a[2 * j + 1]);
            acc_b[2 * j]     = fmaf(pb, fb.x, acc_b[2 * j]);
            acc_b[2 * j + 1] = fmaf(pb, fb.y, acc_b[2 * j + 1]);
        }
    }
    // merge the 4 streams (lanes o, o+8, o+16, o+24)
#pragma unroll
    for (int off = 8; off <= 16; off <<= 1) {
        s_a += __shfl_xor_sync(0xffffffffu, s_a, off);
        s_b += __shfl_xor_sync(0xffffffffu, s_b, off);
#pragma unroll
        for (int j = 0; j < 8; j++) {
            acc_a[j] += __shfl_xor_sync(0xffffffffu, acc_a[j], off);
            acc_b[j] += __shfl_xor_sync(0xffffffffu, acc_b[j], off);
        }
    }

    if (stream == 0) {
        float inv_a = 1.f / s_a;
        float inv_b = 1.f / s_b;
        float4 oa0, oa1, ob0, ob1;
        oa0.x = fmaxf(fmaf(acc_a[0], inv_a, bias1[c_a + 0]), 0.f);
        oa0.y = fmaxf(fmaf(acc_a[1], inv_a, bias1[c_a + 1]), 0.f);
        oa0.z = fmaxf(fmaf(acc_a[2], inv_a, bias1[c_a + 2]), 0.f);
        oa0.w = fmaxf(fmaf(acc_a[3], inv_a, bias1[c_a + 3]), 0.f);
        oa1.x = fmaxf(fmaf(acc_a[4], inv_a, bias1[c_a + 4]), 0.f);
        oa1.y = fmaxf(fmaf(acc_a[5], inv_a, bias1[c_a + 5]), 0.f);
        oa1.z = fmaxf(fmaf(acc_a[6], inv_a, bias1[c_a + 6]), 0.f);
        oa1.w = fmaxf(fmaf(acc_a[7], inv_a, bias1[c_a + 7]), 0.f);
        ob0.x = fmaxf(fmaf(acc_b[0], inv_b, bias1[c_b + 0]), 0.f);
        ob0.y = fmaxf(fmaf(acc_b[1], inv_b, bias1[c_b + 1]), 0.f);
        ob0.z = fmaxf(fmaf(acc_b[2], inv_b, bias1[c_b + 2]), 0.f);
        ob0.w = fmaxf(fmaf(acc_b[3], inv_b, bias1[c_b + 3]), 0.f);
        ob1.x = fmaxf(fmaf(acc_b[4], inv_b, bias1[c_b + 4]), 0.f);
        ob1.y = fmaxf(fmaf(acc_b[5], inv_b, bias1[c_b + 5]), 0.f);
        ob1.z = fmaxf(fmaf(acc_b[6], inv_b, bias1[c_b + 6]), 0.f);
        ob1.w = fmaxf(fmaf(acc_b[7], inv_b, bias1[c_b + 7]), 0.f);
        float4* da = (float4*)&g_h2[(size_t)gw * HID_C + c_a];
        float4* db = (float4*)&g_h2[(size_t)gw * HID_C + c_b];
        da[0] = oa0; da[1] = oa1;
        db[0] = ob0; db[1] = ob1;
    }
}

// ---------------- layer 2: g2 = h2 @ W2 (+ attention scores), node range ----------------
__global__ __launch_bounds__(256) void gemm2_kernel(const float* __restrict__ W2,
                                                    const float* __restrict__ att_src,
                                                    const float* __restrict__ att_dst,
                                                    int nodeBase0, int nodeLimit) {
    __shared__ float Ws[HID_C * OUT_C];
    __shared__ float Hs[16][HID_C];
    int tid = threadIdx.x;
    int nodeBase = nodeBase0 + blockIdx.x * 16;
    for (int i = tid; i < HID_C * OUT_C; i += 256) Ws[i] = W2[i];
    int lnode = tid >> 4;
    int seg = tid & 15;
    int gnode = nodeBase + lnode;
    if (gnode < nodeLimit) {
        *(float4*)&Hs[lnode][seg * 8]     = *(const float4*)&g_h2[(size_t)gnode * HID_C + seg * 8];
        *(float4*)&Hs[lnode][seg * 8 + 4] = *(const float4*)&g_h2[(size_t)gnode * HID_C + seg * 8 + 4];
    }
    __syncthreads();
    int j = tid & 15;
    float acc = 0.f;
#pragma unroll 8
    for (int c = 0; c < HID_C; c++) acc = fmaf(Hs[lnode][c], Ws[c * OUT_C + j], acc);
    float vs = acc * att_src[j];
    float vd = acc * att_dst[j];
#pragma unroll
    for (int off = 8; off; off >>= 1) {
        vs += __shfl_down_sync(0xffffffffu, vs, off, 16);
        vd += __shfl_down_sync(0xffffffffu, vd, off, 16);
    }
    if (gnode < nodeLimit) {
        g_g2h[gnode * OUT_C + j] = __float2half_rn(acc);
        if (j == 0) {
            g_asrc2[gnode] = vs;
            g_adst2[gnode] = vd;
        }
    }
}

// ---------------- layer-2 aggregation: 8 edge streams / warp, uint2 fp16 gather ----------------
__global__ __launch_bounds__(256) void agg2_kernel(const float* __restrict__ bias2,
                                                   float* __restrict__ out, int N) {
    int gw = (blockIdx.x * blockDim.x + threadIdx.x) >> 5;
    if (gw >= N) return;
    int lane = threadIdx.x & 31;
    int stream = lane >> 2;     // 8 streams
    int q = lane & 3;           // channels q*4 .. q*4+3

    float adst = g_adst2[gw];
    int beg = g_rowptr[gw];
    int end = g_rowptr[gw + 1];

    float s = 0.f;
    float a[4] = {0.f, 0.f, 0.f, 0.f};
    if (stream == 0) {  // self loop
        float p0 = __expf(leaky(g_asrc2[gw] + adst));
        uint2 g = *(const uint2*)&g_g2h[gw * OUT_C + q * 4];
        float2 f0 = __half22float2(*(__half2*)&g.x);
        float2 f1 = __half22float2(*(__half2*)&g.y);
        s = p0;
        a[0] = p0 * f0.x; a[1] = p0 * f0.y; a[2] = p0 * f1.x; a[3] = p0 * f1.y;
    }
#pragma unroll 2
    for (int e = beg + stream; e < end; e += 8) {
        int src = g_adj[e];
        float p = __expf(leaky(g_asrc2[src] + adst));
        uint2 g = *(const uint2*)&g_g2h[src * OUT_C + q * 4];
        float2 f0 = __half22float2(*(__half2*)&g.x);
        float2 f1 = __half22float2(*(__half2*)&g.y);
        s += p;
        a[0] = fmaf(p, f0.x, a[0]);
        a[1] = fmaf(p, f0.y, a[1]);
        a[2] = fmaf(p, f1.x, a[2]);
        a[3] = fmaf(p, f1.y, a[3]);
    }
#pragma unroll
    for (int off = 4; off <= 16; off <<= 1) {
        s += __shfl_xor_sync(0xffffffffu, s, off);
        a[0] += __shfl_xor_sync(0xffffffffu, a[0], off);
        a[1] += __shfl_xor_sync(0xffffffffu, a[1], off);
        a[2] += __shfl_xor_sync(0xffffffffu, a[2], off);
        a[3] += __shfl_xor_sync(0xffffffffu, a[3], off);
    }
    if (stream == 0) {
        float inv = 1.f / s;
        float4 o;
        o.x = fmaf(a[0], inv, bias2[q * 4 + 0]);
        o.y = fmaf(a[1], inv, bias2[q * 4 + 1]);
        o.z = fmaf(a[2], inv, bias2[q * 4 + 2]);
        o.w = fmaf(a[3], inv, bias2[q * 4 + 3]);
        *(float4*)&out[gw * OUT_C + q * 4] = o;
    }
}

// ---------------- launch: fork-join graph + agg1/gemm2 half-pipeline ----------------
extern "C" void kernel_launch(void* const* d_in, const int* in_sizes, int n_in,
                              void* d_out, int out_size) {
    const float* x        = (const float*)d_in[0];
    const int*   eidx     = (const int*)d_in[1];
    const float* W1       = (const float*)d_in[2];
    const float* att_src1 = (const float*)d_in[3];
    const float* att_dst1 = (const float*)d_in[4];
    const float* bias1    = (const float*)d_in[5];
    const float* W2       = (const float*)d_in[6];
    const float* att_src2 = (const float*)d_in[7];
    const float* att_dst2 = (const float*)d_in[8];
    const float* bias2    = (const float*)d_in[9];
    float* out = (float*)d_out;

    int N = in_sizes[0] / IN_C;
    int E = in_sizes[1] / 2;
    const int* srcArr = eidx;
    const int* dstArr = eidx + E;
    int Nh = (N / 2 + 15) & ~15;   // half point, 16-aligned for gemm2 blocks

    static cudaStream_t s2 = nullptr;
    static cudaEvent_t evFork = nullptr, evJoin = nullptr, evA = nullptr, evB = nullptr;
    if (!s2) {
        cudaStreamCreateWithFlags(&s2, cudaStreamNonBlocking);
        cudaEventCreateWithFlags(&evFork, cudaEventDisableTiming);
        cudaEventCreateWithFlags(&evJoin, cudaEventDisableTiming);
        cudaEventCreateWithFlags(&evA, cudaEventDisableTiming);
        cudaEventCreateWithFlags(&evB, cudaEventDisableTiming);
    }

    // fork: CSR build on side stream (g_deg self-zeroed by the previous scan_kernel;
    // device globals start zeroed so the first call is also correct)
    cudaEventRecord(evFork, 0);
    cudaStreamWaitEvent(s2, evFork, 0);
    count_kernel<<<(E / 4 + 255) / 256, 256, 0, s2>>>(dstArr, E);
    scan_kernel<<<1, 1024, 0, s2>>>(N);
    scatter_kernel<<<(E / 4 + 255) / 256, 256, 0, s2>>>(srcArr, dstArr, E);
    cudaEventRecord(evJoin, s2);

    // main stream: B fragments, tensor-core GEMM1, attention coefficients
    prep_bfrag_kernel<<<32, 256>>>(W1);
    gemm1_mma_kernel<<<(N + 127) / 128, 256>>>(x, N);
    attn1h_kernel<<<(N * HEADS + 255) / 256, 256>>>(att_src1, att_dst1, N);

    // join CSR
    cudaStreamWaitEvent(0, evJoin, 0);

    // half-pipelined agg1 / gemm2:
    //   main: agg1[0,Nh) -> evA -> agg1[Nh,N) -> gemm2[Nh,N)
    //   s2:   wait evA -> gemm2[0,Nh) -> evB
    agg1_kernel<<<(Nh * 32 + 255) / 256, 256>>>(bias1, 0, Nh);
    cudaEventRecord(evA, 0);
    agg1_kernel<<<((N - Nh) * 32 + 255) / 256, 256>>>(bias1, Nh, N);

    cudaStreamWaitEvent(s2, evA, 0);
    gemm2_kernel<<<Nh / 16, 256, 0, s2>>>(W2, att_src2, att_dst2, 0, Nh);
    cudaEventRecord(evB, s2);

    gemm2_kernel<<<(N - Nh + 15) / 16, 256>>>(W2, att_src2, att_dst2, Nh, N);
    cudaStreamWaitEvent(0, evB, 0);

    agg2_kernel<<<(N * 32 + 255) / 256, 256>>>(bias2, out, N);
}

// round 16
// speedup vs baseline: 1.0568x; 1.0271x over previous
#include <cuda_runtime.h>
#include <cuda_fp16.h>
#include <math_constants.h>
#include <cstdint>

#define N_NODES 50000
#define N_EDGES 1600000
#define IN_C 256
#define HID_C 128
#define OUT_C 16
#define HEADS 8
#define NEG_SLOPE 0.2f

#define N_PAD 53248              // 52 * 1024, for the vectorized scan

// ---------------- scratch (device globals; no allocation allowed) ----------------
__device__ __align__(16) __half g_h1h[N_NODES * HID_C];   // layer-1 features fp16 (gather payload)
__device__ __align__(16) __half g_h2h[N_NODES * HID_C];   // layer-1 output fp16 (post bias+relu)
__device__ __align__(16) __half g_g2h[N_NODES * OUT_C];   // layer-2 features fp16 (gather payload)
__device__ __align__(16) uint2  g_Bfrag[16 * 16 * 32];    // W1 in mma B-fragment layout (64KB)
__device__ float g_asrc1[N_NODES * HEADS];
__device__ float g_adst1[N_NODES * HEADS];
__device__ float g_asrc2[N_NODES];
__device__ float g_adst2[N_NODES];
__device__ int   g_deg[N_PAD];
__device__ int   g_rowptr[N_PAD + 8];
__device__ int   g_cursor[N_PAD + 8];
__device__ int   g_adj[N_EDGES];

__device__ __forceinline__ float leaky(float a) { return (a > 0.f) ? a : NEG_SLOPE * a; }

__device__ __forceinline__ uint32_t smem_u32(const void* p) {
    uint32_t a;
    asm("{ .reg .u64 t; cvta.to.shared.u64 t, %1; cvt.u32.u64 %0, t; }" : "=r"(a) : "l"(p));
    return a;
}

// ---------------- W1 -> mma B-fragment layout (runs once per call, tiny) ----------------
__global__ void prep_bfrag_kernel(const float* __restrict__ W1) {
    int idx = blockIdx.x * blockDim.x + threadIdx.x;   // 8192
    int lane = idx & 31;
    int ntile = (idx >> 5) & 15;
    int kstep = idx >> 9;
    int n = ntile * 8 + (lane >> 2);
    int k0 = kstep * 16 + (lane & 3) * 2;
    __half2 b0 = __floats2half2_rn(W1[k0 * HID_C + n],       W1[(k0 + 1) * HID_C + n]);
    __half2 b1 = __floats2half2_rn(W1[(k0 + 8) * HID_C + n], W1[(k0 + 9) * HID_C + n]);
    uint2 v;
    v.x = *(uint32_t*)&b0;
    v.y = *(uint32_t*)&b1;
    g_Bfrag[idx] = v;
}

// ---------------- GEMM1 via mma.sync (HMMA), register double-buffered ----------------
#define ASTRIDE 40   // halves; 80B row stride -> conflict-free ldmatrix
__global__ __launch_bounds__(256, 2) void gemm1_mma_kernel(const float* __restrict__ A, int M) {
    __shared__ __align__(16) __half As[128][ASTRIDE];
    int tid = threadIdx.x, wid = tid >> 5, lane = tid & 31;
    int warp_m = wid >> 2, warp_n = wid & 3;
    int bm = blockIdx.x * 128;

    float acc[4][4][4];
#pragma unroll
    for (int mt = 0; mt < 4; mt++)
#pragma unroll
        for (int nt = 0; nt < 4; nt++)
#pragma unroll
            for (int r = 0; r < 4; r++) acc[mt][nt][r] = 0.f;

    uint32_t aBase = smem_u32(&As[0][0]) +
                     ((uint32_t)((warp_m * 64 + (lane & 15)) * ASTRIDE + (lane >> 4) * 8) << 1);

    int lr = tid >> 1;
    int lc = (tid & 1) * 16;
    int grow_l = bm + lr;
    const float4* arow = (const float4*)&A[(size_t)grow_l * IN_C];
    bool inM = (grow_l < M);

    float4 v[4];
#pragma unroll
    for (int i = 0; i < 4; i++)
        v[i] = inM ? arow[lc / 4 + i] : make_float4(0.f, 0.f, 0.f, 0.f);

    for (int chunk = 0; chunk < 8; chunk++) {
        {
            uint4 s0, s1;
            __half2 h0 = __floats2half2_rn(v[0].x, v[0].y);
            __half2 h1 = __floats2half2_rn(v[0].z, v[0].w);
            __half2 h2 = __floats2half2_rn(v[1].x, v[1].y);
            __half2 h3 = __floats2half2_rn(v[1].z, v[1].w);
            s0 = make_uint4(*(uint32_t*)&h0, *(uint32_t*)&h1, *(uint32_t*)&h2, *(uint32_t*)&h3);
            __half2 h4 = __floats2half2_rn(v[2].x, v[2].y);
            __half2 h5 = __floats2half2_rn(v[2].z, v[2].w);
            __half2 h6 = __floats2half2_rn(v[3].x, v[3].y);
            __half2 h7 = __floats2half2_rn(v[3].z, v[3].w);
            s1 = make_uint4(*(uint32_t*)&h4, *(uint32_t*)&h5, *(uint32_t*)&h6, *(uint32_t*)&h7);
            *(uint4*)&As[lr][lc]     = s0;
            *(uint4*)&As[lr][lc + 8] = s1;
        }
        __syncthreads();

        float4 vn[4];
#pragma unroll
        for (int i = 0; i < 4; i++)
            vn[i] = (chunk < 7 && inM) ? arow[((chunk + 1) * 32 + lc) / 4 + i]
                                       : make_float4(0.f, 0.f, 0.f, 0.f);

#pragma unroll
        for (int s = 0; s < 2; s++) {
            int ks = chunk * 2 + s;
            uint2 bf[4];
            const uint2* bp = &g_Bfrag[(ks * 16 + warp_n * 4) * 32 + lane];
#pragma unroll
            for (int nt = 0; nt < 4; nt++) bf[nt] = bp[nt * 32];
            uint32_t af[4][4];
#pragma unroll
            for (int mt = 0; mt < 4; mt++) {
                uint32_t addr = aBase + ((uint32_t)(mt * 16 * ASTRIDE + s * 16) << 1);
                asm volatile(
                    "ldmatrix.sync.aligned.m8n8.x4.shared.b16 {%0,%1,%2,%3}, [%4];"
                    : "=r"(af[mt][0]), "=r"(af[mt][1]), "=r"(af[mt][2]), "=r"(af[mt][3])
                    : "r"(addr));
            }
#pragma unroll
            for (int mt = 0; mt < 4; mt++)
#pragma unroll
                for (int nt = 0; nt < 4; nt++)
                    asm volatile(
                        "mma.sync.aligned.m16n8k16.row.col.f32.f16.f16.f32 "
                        "{%0,%1,%2,%3}, {%4,%5,%6,%7}, {%8,%9}, {%0,%1,%2,%3};"
                        : "+f"(acc[mt][nt][0]), "+f"(acc[mt][nt][1]),
                          "+f"(acc[mt][nt][2]), "+f"(acc[mt][nt][3])
                        : "r"(af[mt][0]), "r"(af[mt][1]), "r"(af[mt][2]), "r"(af[mt][3]),
                          "r"(bf[nt].x), "r"(bf[nt].y));
        }
        __syncthreads();
#pragma unroll
        for (int i = 0; i < 4; i++) v[i] = vn[i];
    }

    int r0 = lane >> 2;
    int cq = (lane & 3) * 2;
#pragma unroll
    for (int mt = 0; mt < 4; mt++) {
        int grow0 = bm + warp_m * 64 + mt * 16 + r0;
        int grow1 = grow0 + 8;
#pragma unroll
        for (int nt = 0; nt < 4; nt++) {
            int col = warp_n * 32 + nt * 8 + cq;
            if (grow0 < M) {
                __half2 h = __floats2half2_rn(acc[mt][nt][0], acc[mt][nt][1]);
                *(__half2*)&g_h1h[(size_t)grow0 * HID_C + col] = h;
            }
            if (grow1 < M) {
                __half2 h = __floats2half2_rn(acc[mt][nt][2], acc[mt][nt][3]);
                *(__half2*)&g_h1h[(size_t)grow1 * HID_C + col] = h;
            }
        }
    }
}

// ---------------- attention coefficients from fp16 h1 ----------------
__global__ void attn1h_kernel(const float* __restrict__ att_src,
                              const float* __restrict__ att_dst, int N) {
    int idx = blockIdx.x * blockDim.x + threadIdx.x;  // n*8 + h
    if (idx >= N * HEADS) return;
    int h = idx & 7;
    int n = idx >> 3;
    const uint4* hp = (const uint4*)&g_h1h[(size_t)n * HID_C + h * 16];
    uint4 r0 = hp[0], r1 = hp[1];
    uint32_t raw[8] = {r0.x, r0.y, r0.z, r0.w, r1.x, r1.y, r1.z, r1.w};
    float ss = 0.f, sd = 0.f;
#pragma unroll
    for (int j = 0; j < 8; j++) {
        float2 f = __half22float2(*(__half2*)&raw[j]);
        ss = fmaf(f.x, att_src[h * 16 + 2 * j], ss);
        ss = fmaf(f.y, att_src[h * 16 + 2 * j + 1], ss);
        sd = fmaf(f.x, att_dst[h * 16 + 2 * j], sd);
        sd = fmaf(f.y, att_dst[h * 16 + 2 * j + 1], sd);
    }
    g_asrc1[idx] = ss;
    g_adst1[idx] = sd;
}

// ---------------- CSR build (4 edges / thread) ----------------
__global__ void count_kernel(const int* __restrict__ dst, int E) {
    int base = (blockIdx.x * blockDim.x + threadIdx.x) * 4;
    if (base + 3 < E) {
        int4 d = *(const int4*)&dst[base];
        atomicAdd(&g_deg[d.x], 1);
        atomicAdd(&g_deg[d.y], 1);
        atomicAdd(&g_deg[d.z], 1);
        atomicAdd(&g_deg[d.w], 1);
    } else {
        for (int e = base; e < E; e++) atomicAdd(&g_deg[dst[e]], 1);
    }
}

#define SCAN_CH 52    // 52 * 1024 = N_PAD
__global__ __launch_bounds__(1024) void scan_kernel(int N) {
    __shared__ int sums[1024];
    int t = threadIdx.x;
    int base = t * SCAN_CH;
    int4 buf[SCAN_CH / 4];
    const int4 zero4 = make_int4(0, 0, 0, 0);
#pragma unroll
    for (int i = 0; i < SCAN_CH / 4; i++) {
        buf[i] = *(const int4*)&g_deg[base + i * 4];
        *(int4*)&g_deg[base + i * 4] = zero4;   // self-restore for the next graph replay
    }
    int s = 0;
#pragma unroll
    for (int i = 0; i < SCAN_CH / 4; i++) s += buf[i].x + buf[i].y + buf[i].z + buf[i].w;
    sums[t] = s;
    __syncthreads();
    for (int off = 1; off < 1024; off <<= 1) {
        int v = (t >= off) ? sums[t - off] : 0;
        __syncthreads();
        if (t >= off) sums[t] += v;
        __syncthreads();
    }
    int run = (t == 0) ? 0 : sums[t - 1];
#pragma unroll
    for (int i = 0; i < SCAN_CH / 4; i++) {
        int4 d = buf[i];
        int4 rp;
        rp.x = run; run += d.x;
        rp.y = run; run += d.y;
        rp.z = run; run += d.z;
        rp.w = run; run += d.w;
        *(int4*)&g_rowptr[base + i * 4] = rp;
        *(int4*)&g_cursor[base + i * 4] = rp;
    }
    if (t == 1023) g_rowptr[N_PAD] = sums[1023];
}

__global__ void scatter_kernel(const int* __restrict__ src, const int* __restrict__ dst, int E) {
    int base = (blockIdx.x * blockDim.x + threadIdx.x) * 4;
    if (base + 3 < E) {
        int4 d = *(const int4*)&dst[base];
        int4 sv = *(const int4*)&src[base];
        int p0 = atomicAdd(&g_cursor[d.x], 1);
        int p1 = atomicAdd(&g_cursor[d.y], 1);
        int p2 = atomicAdd(&g_cursor[d.z], 1);
        int p3 = atomicAdd(&g_cursor[d.w], 1);
        g_adj[p0] = sv.x;
        g_adj[p1] = sv.y;
        g_adj[p2] = sv.z;
        g_adj[p3] = sv.w;
    } else {
        for (int e = base; e < E; e++) {
            int pos = atomicAdd(&g_cursor[dst[e]], 1);
            g_adj[pos] = src[e];
        }
    }
}

// ---------------- layer-1 aggregation: 4 edge streams / warp, 2x uint4 fp16 gather ----------------
// lane = 8*stream + o: stream selects the edge stream; lane covers channel octet o
// (head o>>1) and octet o+8 (head 4 + (o>>1)). h2 written as fp16.
__global__ __launch_bounds__(256) void agg1_kernel(const float* __restrict__ bias1, int N) {
    int gw = (blockIdx.x * blockDim.x + threadIdx.x) >> 5;
    if (gw >= N) return;
    int lane = threadIdx.x & 31;
    int stream = lane >> 3;     // 4 streams
    int o = lane & 7;
    int head_a = o >> 1;
    int head_b = head_a + 4;
    int c_a = o * 8;
    int c_b = 64 + o * 8;

    float adst_a = g_adst1[gw * HEADS + head_a];
    float adst_b = g_adst1[gw * HEADS + head_b];

    float s_a = 0.f, s_b = 0.f;
    float acc_a[8], acc_b[8];
#pragma unroll
    for (int j = 0; j < 8; j++) { acc_a[j] = 0.f; acc_b[j] = 0.f; }

    if (stream == 0) {  // self loop
        float pa = __expf(leaky(g_asrc1[gw * HEADS + head_a] + adst_a));
        float pb = __expf(leaky(g_asrc1[gw * HEADS + head_b] + adst_b));
        uint4 ra = *(const uint4*)&g_h1h[(size_t)gw * HID_C + c_a];
        uint4 rb = *(const uint4*)&g_h1h[(size_t)gw * HID_C + c_b];
        s_a = pa; s_b = pb;
        uint32_t wa[4] = {ra.x, ra.y, ra.z, ra.w};
        uint32_t wb[4] = {rb.x, rb.y, rb.z, rb.w};
#pragma unroll
        for (int j = 0; j < 4; j++) {
            float2 fa = __half22float2(*(__half2*)&wa[j]);
            float2 fb = __half22float2(*(__half2*)&wb[j]);
            acc_a[2 * j]     = pa * fa.x;
            acc_a[2 * j + 1] = pa * fa.y;
            acc_b[2 * j]     = pb * fb.x;
            acc_b[2 * j + 1] = pb * fb.y;
        }
    }

    int beg = g_rowptr[gw];
    int end = g_rowptr[gw + 1];
#pragma unroll 2
    for (int e = beg + stream; e < end; e += 4) {
        int src = g_adj[e];
        float asa = g_asrc1[src * HEADS + head_a];
        float asb = g_asrc1[src * HEADS + head_b];
        uint4 ra = *(const uint4*)&g_h1h[(size_t)src * HID_C + c_a];
        uint4 rb = *(const uint4*)&g_h1h[(size_t)src * HID_C + c_b];
        float pa = __expf(leaky(asa + adst_a));
        float pb = __expf(leaky(asb + adst_b));
        s_a += pa; s_b += pb;
        uint32_t wa[4] = {ra.x, ra.y, ra.z, ra.w};
        uint32_t wb[4] = {rb.x, rb.y, rb.z, rb.w};
#pragma unroll
        for (int j = 0; j < 4; j++) {
            float2 fa = __half22float2(*(__half2*)&wa[j]);
            float2 fb = __half22float2(*(__half2*)&wb[j]);
            acc_a[2 * j]     = fmaf(pa, fa.x, acc_a[2 * j]);
            acc_a[2 * j + 1] = fmaf(pa, fa.y, acc_a[2 * j + 1]);
            acc_b[2 * j]     = fmaf(pb, fb.x, acc_b[2 * j]);
            acc_b[2 * j + 1] = fmaf(pb, fb.y, acc_b[2 * j + 1]);
        }
    }
    // merge the 4 streams (lanes o, o+8, o+16, o+24)
#pragma unroll
    for (int off = 8; off <= 16; off <<= 1) {
        s_a += __shfl_xor_sync(0xffffffffu, s_a, off);
        s_b += __shfl_xor_sync(0xffffffffu, s_b, off);
#pragma unroll
        for (int j = 0; j < 8; j++) {
            acc_a[j] += __shfl_xor_sync(0xffffffffu, acc_a[j], off);
            acc_b[j] += __shfl_xor_sync(0xffffffffu, acc_b[j], off);
        }
    }

    if (stream == 0) {
        float inv_a = 1.f / s_a;
        float inv_b = 1.f / s_b;
        uint4 sa, sb;
        {
            __half2 p0 = __floats2half2_rn(fmaxf(fmaf(acc_a[0], inv_a, bias1[c_a + 0]), 0.f),
                                           fmaxf(fmaf(acc_a[1], inv_a, bias1[c_a + 1]), 0.f));
            __half2 p1 = __floats2half2_rn(fmaxf(fmaf(acc_a[2], inv_a, bias1[c_a + 2]), 0.f),
                                           fmaxf(fmaf(acc_a[3], inv_a, bias1[c_a + 3]), 0.f));
            __half2 p2 = __floats2half2_rn(fmaxf(fmaf(acc_a[4], inv_a, bias1[c_a + 4]), 0.f),
                                           fmaxf(fmaf(acc_a[5], inv_a, bias1[c_a + 5]), 0.f));
            __half2 p3 = __floats2half2_rn(fmaxf(fmaf(acc_a[6], inv_a, bias1[c_a + 6]), 0.f),
                                           fmaxf(fmaf(acc_a[7], inv_a, bias1[c_a + 7]), 0.f));
            sa = make_uint4(*(uint32_t*)&p0, *(uint32_t*)&p1, *(uint32_t*)&p2, *(uint32_t*)&p3);
        }
        {
            __half2 p0 = __floats2half2_rn(fmaxf(fmaf(acc_b[0], inv_b, bias1[c_b + 0]), 0.f),
                                           fmaxf(fmaf(acc_b[1], inv_b, bias1[c_b + 1]), 0.f));
            __half2 p1 = __floats2half2_rn(fmaxf(fmaf(acc_b[2], inv_b, bias1[c_b + 2]), 0.f),
                                           fmaxf(fmaf(acc_b[3], inv_b, bias1[c_b + 3]), 0.f));
            __half2 p2 = __floats2half2_rn(fmaxf(fmaf(acc_b[4], inv_b, bias1[c_b + 4]), 0.f),
                                           fmaxf(fmaf(acc_b[5], inv_b, bias1[c_b + 5]), 0.f));
            __half2 p3 = __floats2half2_rn(fmaxf(fmaf(acc_b[6], inv_b, bias1[c_b + 6]), 0.f),
                                           fmaxf(fmaf(acc_b[7], inv_b, bias1[c_b + 7]), 0.f));
            sb = make_uint4(*(uint32_t*)&p0, *(uint32_t*)&p1, *(uint32_t*)&p2, *(uint32_t*)&p3);
        }
        *(uint4*)&g_h2h[(size_t)gw * HID_C + c_a] = sa;
        *(uint4*)&g_h2h[(size_t)gw * HID_C + c_b] = sb;
    }
}

// ---------------- layer 2: g2 = h2h @ W2 (+ attention scores), fused, fp16 in/out ----------------
__global__ __launch_bounds__(256) void gemm2_kernel(const float* __restrict__ W2,
                                                    const float* __restrict__ att_src,
                                                    const float* __restrict__ att_dst, int N) {
    __shared__ float Ws[HID_C * OUT_C];
    __shared__ float Hs[16][HID_C];
    int tid = threadIdx.x;
    int nodeBase = blockIdx.x * 16;
    for (int i = tid; i < HID_C * OUT_C; i += 256) Ws[i] = W2[i];
    int lnode = tid >> 4;
    int seg = tid & 15;
    int gnode = nodeBase + lnode;
    if (gnode < N) {
        uint4 raw = *(const uint4*)&g_h2h[(size_t)gnode * HID_C + seg * 8];
        uint32_t w[4] = {raw.x, raw.y, raw.z, raw.w};
#pragma unroll
        for (int j = 0; j < 4; j++) {
            float2 f = __half22float2(*(__half2*)&w[j]);
            Hs[lnode][seg * 8 + 2 * j]     = f.x;
            Hs[lnode][seg * 8 + 2 * j + 1] = f.y;
        }
    }
    __syncthreads();
    int j = tid & 15;
    float acc = 0.f;
#pragma unroll 8
    for (int c = 0; c < HID_C; c++) acc = fmaf(Hs[lnode][c], Ws[c * OUT_C + j], acc);
    float vs = acc * att_src[j];
    float vd = acc * att_dst[j];
#pragma unroll
    for (int off = 8; off; off >>= 1) {
        vs += __shfl_down_sync(0xffffffffu, vs, off, 16);
        vd += __shfl_down_sync(0xffffffffu, vd, off, 16);
    }
    if (gnode < N) {
        g_g2h[gnode * OUT_C + j] = __float2half_rn(acc);
        if (j == 0) {
            g_asrc2[gnode] = vs;
            g_adst2[gnode] = vd;
        }
    }
}

// ---------------- layer-2 aggregation: 8 edge streams / warp, uint2 fp16 gather ----------------
__global__ __launch_bounds__(256) void agg2_kernel(const float* __restrict__ bias2,
                                                   float* __restrict__ out, int N) {
    int gw = (blockIdx.x * blockDim.x + threadIdx.x) >> 5;
    if (gw >= N) return;
    int lane = threadIdx.x & 31;
    int stream = lane >> 2;     // 8 streams
    int q = lane & 3;           // channels q*4 .. q*4+3

    float adst = g_adst2[gw];
    int beg = g_rowptr[gw];
    int end = g_rowptr[gw + 1];

    float s = 0.f;
    float a[4] = {0.f, 0.f, 0.f, 0.f};
    if (stream == 0) {  // self loop
        float p0 = __expf(leaky(g_asrc2[gw] + adst));
        uint2 g = *(const uint2*)&g_g2h[gw * OUT_C + q * 4];
        float2 f0 = __half22float2(*(__half2*)&g.x);
        float2 f1 = __half22float2(*(__half2*)&g.y);
        s = p0;
        a[0] = p0 * f0.x; a[1] = p0 * f0.y; a[2] = p0 * f1.x; a[3] = p0 * f1.y;
    }
#pragma unroll 2
    for (int e = beg + stream; e < end; e += 8) {
        int src = g_adj[e];
        float p = __expf(leaky(g_asrc2[src] + adst));
        uint2 g = *(const uint2*)&g_g2h[src * OUT_C + q * 4];
        float2 f0 = __half22float2(*(__half2*)&g.x);
        float2 f1 = __half22float2(*(__half2*)&g.y);
        s += p;
        a[0] = fmaf(p, f0.x, a[0]);
        a[1] = fmaf(p, f0.y, a[1]);
        a[2] = fmaf(p, f1.x, a[2]);
        a[3] = fmaf(p, f1.y, a[3]);
    }
#pragma unroll
    for (int off = 4; off <= 16; off <<= 1) {
        s += __shfl_xor_sync(0xffffffffu, s, off);
        a[0] += __shfl_xor_sync(0xffffffffu, a[0], off);
        a[1] += __shfl_xor_sync(0xffffffffu, a[1], off);
        a[2] += __shfl_xor_sync(0xffffffffu, a[2], off);
        a[3] += __shfl_xor_sync(0xffffffffu, a[3], off);
    }
    if (stream == 0) {
        float inv = 1.f / s;
        float4 o;
        o.x = fmaf(a[0], inv, bias2[q * 4 + 0]);
        o.y = fmaf(a[1], inv, bias2[q * 4 + 1]);
        o.z = fmaf(a[2], inv, bias2[q * 4 + 2]);
        o.w = fmaf(a[3], inv, bias2[q * 4 + 3]);
        *(float4*)&out[gw * OUT_C + q * 4] = o;
    }
}

// ---------------- launch: fork-join graph ----------------
extern "C" void kernel_launch(void* const* d_in, const int* in_sizes, int n_in,
                              void* d_out, int out_size) {
    const float* x        = (const float*)d_in[0];
    const int*   eidx     = (const int*)d_in[1];
    const float* W1       = (const float*)d_in[2];
    const float* att_src1 = (const float*)d_in[3];
    const float* att_dst1 = (const float*)d_in[4];
    const float* bias1    = (const float*)d_in[5];
    const float* W2       = (const float*)d_in[6];
    const float* att_src2 = (const float*)d_in[7];
    const float* att_dst2 = (const float*)d_in[8];
    const float* bias2    = (const float*)d_in[9];
    float* out = (float*)d_out;

    int N = in_sizes[0] / IN_C;
    int E = in_sizes[1] / 2;
    const int* srcArr = eidx;
    const int* dstArr = eidx + E;

    static cudaStream_t s2 = nullptr;
    static cudaEvent_t evFork = nullptr, evJoin = nullptr;
    if (!s2) {
        cudaStreamCreateWithFlags(&s2, cudaStreamNonBlocking);
        cudaEventCreateWithFlags(&evFork, cudaEventDisableTiming);
        cudaEventCreateWithFlags(&evJoin, cudaEventDisableTiming);
    }

    // fork: CSR build on side stream (g_deg self-zeroed by the previous scan_kernel;
    // device globals start zeroed so the first call is also correct)
    cudaEventRecord(evFork, 0);
    cudaStreamWaitEvent(s2, evFork, 0);
    count_kernel<<<(E / 4 + 255) / 256, 256, 0, s2>>>(dstArr, E);
    scan_kernel<<<1, 1024, 0, s2>>>(N);
    scatter_kernel<<<(E / 4 + 255) / 256, 256, 0, s2>>>(srcArr, dstArr, E);
    cudaEventRecord(evJoin, s2);

    // main stream: B fragments, tensor-core GEMM1, attention coefficients
    prep_bfrag_kernel<<<32, 256>>>(W1);
    gemm1_mma_kernel<<<(N + 127) / 128, 256>>>(x, N);
    attn1h_kernel<<<(N * HEADS + 255) / 256, 256>>>(att_src1, att_dst1, N);

    // join
    cudaStreamWaitEvent(0, evJoin, 0);

    agg1_kernel<<<(N * 32 + 255) / 256, 256>>>(bias1, N);
    gemm2_kernel<<<(N + 15) / 16, 256>>>(W2, att_src2, att_dst2, N);
    agg2_kernel<<<(N * 32 + 255) / 256, 256>>>(bias2, out, N);
}